// round 7
// baseline (speedup 1.0000x reference)
#include <cuda_runtime.h>
#include <math.h>
#include <stdint.h>

#define N_NODES 50000
#define N_EDGES 800000
#define IN_F    256
#define OUT_F   64
#define HEADS   4
#define HO      256
#define NEG_SLOPE 0.2f

#define SCAN_BLK 256
#define NSCAN ((N_NODES + SCAN_BLK - 1) / SCAN_BLK)   // 196

// ---------------- scratch (static device globals) --------------------------
__device__ float g_h[(size_t)N_NODES * HO];        // 51.2 MB projected features
__device__ float g_attn_src[N_NODES * HEADS];
__device__ float g_attn_dst[N_NODES * HEADS];
__device__ float g_es[(size_t)N_EDGES * HEADS];    // scores in CSR order
__device__ int   g_max_bits;
__device__ int   g_deg[N_NODES];
__device__ int   g_scan[N_NODES];
__device__ int   g_bsum[NSCAN];
__device__ int   g_rowstart[N_NODES];
__device__ int   g_ptr[N_NODES];
__device__ int   g_sorted_src[N_EDGES];

// ---------------- kernel 0: init ------------------------------------------
__global__ void init_kernel() {
    int i = blockIdx.x * blockDim.x + threadIdx.x;
    if (i == 0) g_max_bits = 0xFF800000; // -inf
    if (i < N_NODES) g_deg[i] = 0;
}

// ---------------- kernel: dst histogram ------------------------------------
__global__ void hist_kernel(const int* __restrict__ ei) {
    int e = blockIdx.x * blockDim.x + threadIdx.x;
    if (e < N_EDGES) atomicAdd(&g_deg[ei[N_EDGES + e]], 1);
}

// ---------------- scan kernels ----------------------------------------------
__global__ void scan1_kernel() {
    __shared__ int s[SCAN_BLK];
    int t = threadIdx.x;
    int i = blockIdx.x * SCAN_BLK + t;
    int v = (i < N_NODES) ? g_deg[i] : 0;
    s[t] = v;
    __syncthreads();
    #pragma unroll
    for (int off = 1; off < SCAN_BLK; off <<= 1) {
        int tmp = (t >= off) ? s[t - off] : 0;
        __syncthreads();
        if (t >= off) s[t] += tmp;
        __syncthreads();
    }
    if (i < N_NODES) g_scan[i] = s[t];
    if (t == SCAN_BLK - 1) g_bsum[blockIdx.x] = s[t];
}
__global__ void scan2_kernel() {   // 1 block, NSCAN <= 256
    __shared__ int s[SCAN_BLK];
    int t = threadIdx.x;
    int v = (t < NSCAN) ? g_bsum[t] : 0;
    s[t] = v;
    __syncthreads();
    #pragma unroll
    for (int off = 1; off < SCAN_BLK; off <<= 1) {
        int tmp = (t >= off) ? s[t - off] : 0;
        __syncthreads();
        if (t >= off) s[t] += tmp;
        __syncthreads();
    }
    if (t < NSCAN) g_bsum[t] = s[t] - v;   // exclusive
}
__global__ void scan3_kernel() {
    int i = blockIdx.x * SCAN_BLK + threadIdx.x;
    if (i < N_NODES) {
        int rs = g_scan[i] - g_deg[i] + g_bsum[blockIdx.x];
        g_rowstart[i] = rs;
        g_ptr[i] = rs;
    }
}

// ---------------- GEMM: h = x @ Wc (all heads fused), proven R2 kernel ------
#define GBM 128
#define GBN 128
#define GBK 8
#define KTILES (IN_F / GBK)   // 32

__global__ void __launch_bounds__(256) gemm_kernel(const float* __restrict__ x,
                                                   const float* __restrict__ W) {
    __shared__ __align__(16) float As[2][GBK][GBM + 4];
    __shared__ __align__(16) float Bs[2][GBK][GBN];

    const int m0 = blockIdx.x * GBM;
    const int n0 = blockIdx.y * GBN;
    const int t  = threadIdx.x;

    // A-load mapping: thread -> (row, 4-wide k chunk)
    const int am = t >> 1;            // 0..127
    const int ak = (t & 1) << 2;      // 0 or 4
    const int gm = m0 + am;
    const bool a_ok = (gm < N_NODES);
    const float* Aptr = x + (size_t)gm * IN_F + ak;

    // B-load mapping: thread -> (k row, 4-wide n chunk); resolve head once
    const int bk = t >> 5;            // 0..7
    const int bn = (t & 31) << 2;     // 0..124
    const int nb = n0 + bn;
    const float* Bptr = W + (size_t)(nb >> 6) * IN_F * OUT_F + (nb & 63); // + k*64

    float4 rA, rB;
    rA = a_ok ? *(const float4*)(Aptr) : make_float4(0.f, 0.f, 0.f, 0.f);
    rB = *(const float4*)(Bptr + (size_t)bk * OUT_F);
    As[0][ak + 0][am] = rA.x; As[0][ak + 1][am] = rA.y;
    As[0][ak + 2][am] = rA.z; As[0][ak + 3][am] = rA.w;
    *(float4*)&Bs[0][bk][bn] = rB;
    __syncthreads();

    const int tx = t & 15;
    const int ty = t >> 4;
    float acc[8][8] = {};

    for (int kt = 0; kt < KTILES; kt++) {
        const int cur = kt & 1;
        if (kt + 1 < KTILES) {
            const int k0 = (kt + 1) * GBK;
            rA = a_ok ? *(const float4*)(Aptr + k0) : make_float4(0.f, 0.f, 0.f, 0.f);
            rB = *(const float4*)(Bptr + (size_t)(k0 + bk) * OUT_F);
        }
        #pragma unroll
        for (int k = 0; k < GBK; k++) {
            float4 a0 = *(const float4*)&As[cur][k][ty << 2];
            float4 a1 = *(const float4*)&As[cur][k][(ty << 2) + 64];
            float4 b0 = *(const float4*)&Bs[cur][k][tx << 2];
            float4 b1 = *(const float4*)&Bs[cur][k][(tx << 2) + 64];
            float a[8] = {a0.x, a0.y, a0.z, a0.w, a1.x, a1.y, a1.z, a1.w};
            float b[8] = {b0.x, b0.y, b0.z, b0.w, b1.x, b1.y, b1.z, b1.w};
            #pragma unroll
            for (int i = 0; i < 8; i++)
                #pragma unroll
                for (int j = 0; j < 8; j++)
                    acc[i][j] = fmaf(a[i], b[j], acc[i][j]);
        }
        if (kt + 1 < KTILES) {
            const int nxt = cur ^ 1;
            As[nxt][ak + 0][am] = rA.x; As[nxt][ak + 1][am] = rA.y;
            As[nxt][ak + 2][am] = rA.z; As[nxt][ak + 3][am] = rA.w;
            *(float4*)&Bs[nxt][bk][bn] = rB;
            __syncthreads();
        }
    }

    #pragma unroll
    for (int i = 0; i < 8; i++) {
        int row = m0 + ((i < 4) ? (ty << 2) + i : 60 + (ty << 2) + i);
        if (row < N_NODES) {
            float* dst = g_h + (size_t)row * HO + n0;
            *(float4*)(dst + (tx << 2))      = make_float4(acc[i][0], acc[i][1], acc[i][2], acc[i][3]);
            *(float4*)(dst + (tx << 2) + 64) = make_float4(acc[i][4], acc[i][5], acc[i][6], acc[i][7]);
        }
    }
}

// ---------------- kernel: per-node attention logits (proven R2 kernel) ------
__global__ void attn_kernel(const float* __restrict__ a_src,
                            const float* __restrict__ a_dst) {
    int gw   = (blockIdx.x * blockDim.x + threadIdx.x) >> 5;
    int lane = threadIdx.x & 31;
    if (gw >= N_NODES * HEADS) return;
    int n = gw >> 2;
    int h = gw & 3;

    const float2* hv = (const float2*)(g_h + (size_t)n * HO + h * OUT_F);
    const float2* as = (const float2*)(a_src + h * OUT_F);
    const float2* ad = (const float2*)(a_dst + h * OUT_F);
    float2 v = hv[lane];
    float2 s2 = as[lane];
    float2 d2 = ad[lane];
    float s = v.x * s2.x + v.y * s2.y;
    float d = v.x * d2.x + v.y * d2.y;
    #pragma unroll
    for (int o = 16; o; o >>= 1) {
        s += __shfl_xor_sync(0xFFFFFFFFu, s, o);
        d += __shfl_xor_sync(0xFFFFFFFFu, d, o);
    }
    if (lane == 0) {
        g_attn_src[n * HEADS + h] = s;
        g_attn_dst[n * HEADS + h] = d;
    }
}

// ---------------- kernel: bucket edges by dst + compute scores + max --------
__device__ __forceinline__ float leaky(float v) { return v >= 0.0f ? v : NEG_SLOPE * v; }

__device__ void atomic_max_float(int* addr, float value) {
    int old = *addr;
    while (__int_as_float(old) < value) {
        int assumed = old;
        old = atomicCAS(addr, assumed, __float_as_int(value));
        if (old == assumed) break;
    }
}

__global__ void sort_score_kernel(const int* __restrict__ ei,
                                  const float* __restrict__ ew) {
    int e = blockIdx.x * blockDim.x + threadIdx.x;
    float local = -INFINITY;
    if (e < N_EDGES) {
        int src = ei[e];
        int dst = ei[N_EDGES + e];
        float w = ew[e];
        float4 as = *(const float4*)(g_attn_src + src * 4);
        float4 ad = *(const float4*)(g_attn_dst + dst * 4);
        float4 r;
        r.x = leaky(as.x + ad.x) * w;
        r.y = leaky(as.y + ad.y) * w;
        r.z = leaky(as.z + ad.z) * w;
        r.w = leaky(as.w + ad.w) * w;
        int pos = atomicAdd(&g_ptr[dst], 1);
        g_sorted_src[pos] = src;
        *(float4*)(g_es + (size_t)pos * 4) = r;
        local = fmaxf(fmaxf(r.x, r.y), fmaxf(r.z, r.w));
    }
    #pragma unroll
    for (int o = 16; o; o >>= 1)
        local = fmaxf(local, __shfl_xor_sync(0xFFFFFFFFu, local, o));
    if ((threadIdx.x & 31) == 0 && local > -INFINITY)
        atomic_max_float(&g_max_bits, local);
}

// ---------------- kernel: gather-aggregate (proven R2 kernel, contiguous es)
__global__ void __launch_bounds__(256) aggregate_kernel(float* __restrict__ out) {
    int n    = (blockIdx.x * blockDim.x + threadIdx.x) >> 5;
    int lane = threadIdx.x & 31;
    if (n >= N_NODES) return;

    const int start = g_rowstart[n];
    const int deg   = g_deg[n];
    const float m   = __int_as_float(g_max_bits);

    float4 acc0 = make_float4(0.f, 0.f, 0.f, 0.f);
    float4 acc1 = make_float4(0.f, 0.f, 0.f, 0.f);
    float4 ds   = make_float4(0.f, 0.f, 0.f, 0.f);

    for (int i = 0; i < deg; i++) {
        int idx = start + i;
        int src = __ldg(&g_sorted_src[idx]);
        float4 sc = *(const float4*)(g_es + (size_t)idx * 4);   // contiguous
        float4 ee;
        ee.x = __expf(sc.x - m);
        ee.y = __expf(sc.y - m);
        ee.z = __expf(sc.z - m);
        ee.w = __expf(sc.w - m);
        ds.x += ee.x; ds.y += ee.y; ds.z += ee.z; ds.w += ee.w;

        float alo = (lane < 16) ? ee.x : ee.y;   // heads 0/1
        float ahi = (lane < 16) ? ee.z : ee.w;   // heads 2/3
        const float4* hs = (const float4*)(g_h + (size_t)src * HO);
        float4 v0 = hs[lane];
        float4 v1 = hs[lane + 32];
        acc0.x = fmaf(v0.x, alo, acc0.x);
        acc0.y = fmaf(v0.y, alo, acc0.y);
        acc0.z = fmaf(v0.z, alo, acc0.z);
        acc0.w = fmaf(v0.w, alo, acc0.w);
        acc1.x = fmaf(v1.x, ahi, acc1.x);
        acc1.y = fmaf(v1.y, ahi, acc1.y);
        acc1.z = fmaf(v1.z, ahi, acc1.z);
        acc1.w = fmaf(v1.w, ahi, acc1.w);
    }

    float dlo = 1.0f / (((lane < 16) ? ds.x : ds.y) + 1e-10f);
    float dhi = 1.0f / (((lane < 16) ? ds.z : ds.w) + 1e-10f);
    float4* od = (float4*)(out + (size_t)n * HO);
    od[lane]      = make_float4(acc0.x * dlo, acc0.y * dlo, acc0.z * dlo, acc0.w * dlo);
    od[lane + 32] = make_float4(acc1.x * dhi, acc1.y * dhi, acc1.z * dhi, acc1.w * dhi);
}

// ---------------- launch -----------------------------------------------------
extern "C" void kernel_launch(void* const* d_in, const int* in_sizes, int n_in,
                              void* d_out, int out_size) {
    const float* x     = (const float*)d_in[0];
    const int*   eidx  = (const int*)  d_in[1];
    const float* ew    = (const float*)d_in[2];
    const float* W     = (const float*)d_in[3];
    const float* a_src = (const float*)d_in[4];
    const float* a_dst = (const float*)d_in[5];
    float* out = (float*)d_out;

    init_kernel<<<NSCAN, SCAN_BLK>>>();
    hist_kernel<<<(N_EDGES + 255) / 256, 256>>>(eidx);
    scan1_kernel<<<NSCAN, SCAN_BLK>>>();
    scan2_kernel<<<1, SCAN_BLK>>>();
    scan3_kernel<<<NSCAN, SCAN_BLK>>>();

    dim3 ggrid((N_NODES + GBM - 1) / GBM, HO / GBN);
    gemm_kernel<<<ggrid, 256>>>(x, W);

    attn_kernel<<<(N_NODES * HEADS * 32 + 255) / 256, 256>>>(a_src, a_dst);

    sort_score_kernel<<<(N_EDGES + 255) / 256, 256>>>(eidx, ew);

    aggregate_kernel<<<(N_NODES * 32 + 255) / 256, 256>>>(out);
}

// round 8
// speedup vs baseline: 1.8857x; 1.8857x over previous
#include <cuda_runtime.h>
#include <cuda_bf16.h>
#include <math.h>
#include <stdint.h>

#define N_NODES 50000
#define N_EDGES 800000
#define IN_F    256
#define OUT_F   64
#define HEADS   4
#define HO      256
#define NEG_SLOPE 0.2f

#define SCAN_BLK 256
#define NSCAN ((N_NODES + SCAN_BLK - 1) / SCAN_BLK)   // 196

// ---------------- scratch (static device globals) --------------------------
__device__ float g_h[(size_t)N_NODES * HO];        // 51.2 MB projected features
__device__ float g_attn_src[N_NODES * HEADS];
__device__ float g_attn_dst[N_NODES * HEADS];
__device__ float g_e[(size_t)N_EDGES * HEADS];     // scores by edge id (seq)
__device__ int   g_max_bits;
__device__ int   g_deg[N_NODES];
__device__ int   g_scan[N_NODES];
__device__ int   g_bsum[NSCAN];
__device__ int   g_rowstart[N_NODES];
__device__ int   g_ptr[N_NODES];
__device__ int   g_sorted_src[N_EDGES];
__device__ int   g_sorted_eid[N_EDGES];
// bf16-split B images in mma-ready padded layout: [8 chunks][256 n][20 words]
__device__ uint32_t g_Bhi[8 * 256 * 20];
__device__ uint32_t g_Blo[8 * 256 * 20];

// ---------------- helpers ----------------------------------------------------
__device__ __forceinline__ uint32_t smem_u32(const void* p) {
    uint32_t a;
    asm("{ .reg .u64 t; cvta.to.shared.u64 t, %1; cvt.u32.u64 %0, t; }" : "=r"(a) : "l"(p));
    return a;
}
__device__ __forceinline__ uint32_t pack2(float a, float b) {
    __nv_bfloat162 h = __floats2bfloat162_rn(a, b);
    return *(uint32_t*)&h;
}
__device__ __forceinline__ void split2(float v, float& hi, float& lo) {
    hi = __bfloat162float(__float2bfloat16(v));
    lo = v - hi;
}
__device__ __forceinline__ void ldm4(uint32_t& r0, uint32_t& r1, uint32_t& r2, uint32_t& r3,
                                     uint32_t addr) {
    asm volatile("ldmatrix.sync.aligned.m8n8.x4.shared.b16 {%0,%1,%2,%3}, [%4];"
                 : "=r"(r0), "=r"(r1), "=r"(r2), "=r"(r3) : "r"(addr));
}
__device__ __forceinline__ void mma16816(float* c, const uint32_t* a, const uint32_t* b) {
    asm("mma.sync.aligned.m16n8k16.row.col.f32.bf16.bf16.f32 "
        "{%0,%1,%2,%3},{%4,%5,%6,%7},{%8,%9},{%0,%1,%2,%3};"
        : "+f"(c[0]), "+f"(c[1]), "+f"(c[2]), "+f"(c[3])
        : "r"(a[0]), "r"(a[1]), "r"(a[2]), "r"(a[3]), "r"(b[0]), "r"(b[1]));
}

// ---------------- kernel 0: init ------------------------------------------
__global__ void init_kernel() {
    int i = blockIdx.x * blockDim.x + threadIdx.x;
    if (i == 0) g_max_bits = 0xFF800000; // -inf
    if (i < N_NODES) g_deg[i] = 0;
}

// ---------------- kernel: precompute split B images -------------------------
// Wc[k][n] = W[n>>6][k][n&63]; layout: [chunk c][n][20 words], word kp packs k=2kp,2kp+1
__global__ void prep_b_kernel(const float* __restrict__ W) {
    int tid = blockIdx.x * blockDim.x + threadIdx.x;   // 32768
    int c  = tid >> 12;
    int r  = tid & 4095;
    int n  = r >> 4;
    int kp = r & 15;
    int k0 = c * 32 + kp * 2;
    const float* Wn = W + (size_t)(n >> 6) * IN_F * OUT_F + (n & 63);
    float v0 = Wn[(size_t)k0 * OUT_F];
    float v1 = Wn[(size_t)(k0 + 1) * OUT_F];
    float h0, l0, h1, l1;
    split2(v0, h0, l0);
    split2(v1, h1, l1);
    int w = (c * 256 + n) * 20 + kp;
    g_Bhi[w] = pack2(h0, h1);
    g_Blo[w] = pack2(l0, l1);
}

// ---------------- GEMM: mma.sync bf16, 2-way split, 3 products --------------
// CTA tile 128m x 128n, K-chunks of 32; 8 warps = 2(M) x 4(N), warp 64x32
#define ASTRIDE_W 20          // words per smem row (80 B)
#define SM_AH 0
#define SM_AL 2560
#define SM_BH 5120
#define SM_BL 7680

__global__ void __launch_bounds__(256) gemm_mma_kernel(const float* __restrict__ x) {
    __shared__ __align__(16) uint32_t sm[4 * 2560];   // 40 KB
    const int t    = threadIdx.x;
    const int lane = t & 31;
    const int wid  = t >> 5;
    const int m0   = blockIdx.x * 128;
    const int n0   = blockIdx.y * 128;
    const int mw   = (wid >> 2) * 64;   // warp M offset in tile
    const int nw   = (wid & 3) * 32;    // warp N offset in tile
    const uint32_t sb = smem_u32(sm);

    float acc[4][4][4] = {};

    // per-lane ldmatrix address components (constant across chunks)
    const uint32_t a_row  = (uint32_t)(lane & 15);
    const uint32_t a_colb = (uint32_t)((lane >> 4) << 4);          // 0 or 16
    const uint32_t b_row  = (uint32_t)((lane & 7) + ((lane & 16) ? 8 : 0));
    const uint32_t b_colb = (uint32_t)((lane & 8) ? 16 : 0);

    for (int c = 0; c < 8; c++) {
        // ---- A fill: 128 rows x 32 k, fp32 -> bf16 hi/lo ----
        #pragma unroll
        for (int it = 0; it < 4; it++) {
            int f   = t + 256 * it;      // 0..1023 float4s
            int row = f >> 3;
            int kq  = f & 7;
            float4 v = make_float4(0.f, 0.f, 0.f, 0.f);
            if (m0 + row < N_NODES)
                v = *(const float4*)(x + (size_t)(m0 + row) * IN_F + c * 32 + kq * 4);
            float hx, lx, hy, ly, hz, lz, hw, lw;
            split2(v.x, hx, lx); split2(v.y, hy, ly);
            split2(v.z, hz, lz); split2(v.w, hw, lw);
            int off = row * ASTRIDE_W + kq * 2;
            *(uint2*)(sm + SM_AH + off) = make_uint2(pack2(hx, hy), pack2(hz, hw));
            *(uint2*)(sm + SM_AL + off) = make_uint2(pack2(lx, ly), pack2(lz, lw));
        }
        // ---- B fill: copy padded global images (words 0..15 of each row) ----
        #pragma unroll
        for (int it = 0; it < 2; it++) {
            int idx = t + 256 * it;      // 0..511
            int row = idx >> 2;
            int q   = idx & 3;
            int soff = row * ASTRIDE_W + q * 4;
            int goff = (c * 256 + n0 + row) * 20 + q * 4;
            *(uint4*)(sm + SM_BH + soff) = *(const uint4*)(g_Bhi + goff);
            *(uint4*)(sm + SM_BL + soff) = *(const uint4*)(g_Blo + goff);
        }
        __syncthreads();

        // ---- compute: 2 k16-steps ----
        #pragma unroll
        for (int ks = 0; ks < 2; ks++) {
            uint32_t ah[4][4], al[4][4];
            #pragma unroll
            for (int i = 0; i < 4; i++) {
                uint32_t aoff = (mw + i * 16 + a_row) * 80 + ks * 32 + a_colb;
                ldm4(ah[i][0], ah[i][1], ah[i][2], ah[i][3], sb + SM_AH * 4 + aoff);
                ldm4(al[i][0], al[i][1], al[i][2], al[i][3], sb + SM_AL * 4 + aoff);
            }
            uint32_t bh[4][2], bl[4][2];
            #pragma unroll
            for (int j2 = 0; j2 < 2; j2++) {
                uint32_t boff = (nw + j2 * 16 + b_row) * 80 + ks * 32 + b_colb;
                ldm4(bh[2 * j2][0], bh[2 * j2][1], bh[2 * j2 + 1][0], bh[2 * j2 + 1][1],
                     sb + SM_BH * 4 + boff);
                ldm4(bl[2 * j2][0], bl[2 * j2][1], bl[2 * j2 + 1][0], bl[2 * j2 + 1][1],
                     sb + SM_BL * 4 + boff);
            }
            #pragma unroll
            for (int i = 0; i < 4; i++)
                #pragma unroll
                for (int j = 0; j < 4; j++) {
                    mma16816(acc[i][j], ah[i], bh[j]);
                    mma16816(acc[i][j], ah[i], bl[j]);
                    mma16816(acc[i][j], al[i], bh[j]);
                }
        }
        __syncthreads();
    }

    // ---- epilogue ----
    #pragma unroll
    for (int i = 0; i < 4; i++) {
        int row = m0 + mw + i * 16 + (lane >> 2);
        #pragma unroll
        for (int j = 0; j < 4; j++) {
            int col = n0 + nw + j * 8 + (lane & 3) * 2;
            if (row < N_NODES)
                *(float2*)(g_h + (size_t)row * HO + col) = make_float2(acc[i][j][0], acc[i][j][1]);
            if (row + 8 < N_NODES)
                *(float2*)(g_h + (size_t)(row + 8) * HO + col) = make_float2(acc[i][j][2], acc[i][j][3]);
        }
    }
}

// ---------------- kernel: per-node attention logits (proven R2) -------------
__global__ void attn_kernel(const float* __restrict__ a_src,
                            const float* __restrict__ a_dst) {
    int gw   = (blockIdx.x * blockDim.x + threadIdx.x) >> 5;
    int lane = threadIdx.x & 31;
    if (gw >= N_NODES * HEADS) return;
    int n = gw >> 2;
    int h = gw & 3;

    const float2* hv = (const float2*)(g_h + (size_t)n * HO + h * OUT_F);
    const float2* as = (const float2*)(a_src + h * OUT_F);
    const float2* ad = (const float2*)(a_dst + h * OUT_F);
    float2 v = hv[lane];
    float2 s2 = as[lane];
    float2 d2 = ad[lane];
    float s = v.x * s2.x + v.y * s2.y;
    float d = v.x * d2.x + v.y * d2.y;
    #pragma unroll
    for (int o = 16; o; o >>= 1) {
        s += __shfl_xor_sync(0xFFFFFFFFu, s, o);
        d += __shfl_xor_sync(0xFFFFFFFFu, d, o);
    }
    if (lane == 0) {
        g_attn_src[n * HEADS + h] = s;
        g_attn_dst[n * HEADS + h] = d;
    }
}

// ---------------- kernel: edge scores + global max + dst histogram (R2) -----
__device__ __forceinline__ float leaky(float v) { return v >= 0.0f ? v : NEG_SLOPE * v; }

__device__ void atomic_max_float(int* addr, float value) {
    int old = *addr;
    while (__int_as_float(old) < value) {
        int assumed = old;
        old = atomicCAS(addr, assumed, __float_as_int(value));
        if (old == assumed) break;
    }
}

__global__ void edge_score_kernel(const int* __restrict__ edge_index,
                                  const float* __restrict__ ew) {
    int e = blockIdx.x * blockDim.x + threadIdx.x;
    float local = -INFINITY;
    if (e < N_EDGES) {
        int src = edge_index[e];
        int dst = edge_index[N_EDGES + e];
        atomicAdd(&g_deg[dst], 1);
        float w = ew[e];
        float4 as = *(const float4*)(g_attn_src + src * 4);
        float4 ad = *(const float4*)(g_attn_dst + dst * 4);
        float4 r;
        r.x = leaky(as.x + ad.x) * w;
        r.y = leaky(as.y + ad.y) * w;
        r.z = leaky(as.z + ad.z) * w;
        r.w = leaky(as.w + ad.w) * w;
        *(float4*)(g_e + (size_t)e * 4) = r;   // sequential by edge id
        local = fmaxf(fmaxf(r.x, r.y), fmaxf(r.z, r.w));
    }
    #pragma unroll
    for (int o = 16; o; o >>= 1)
        local = fmaxf(local, __shfl_xor_sync(0xFFFFFFFFu, local, o));
    if ((threadIdx.x & 31) == 0 && local > -INFINITY)
        atomic_max_float(&g_max_bits, local);
}

// ---------------- scan kernels (proven R2) -----------------------------------
__global__ void scan1_kernel() {
    __shared__ int s[SCAN_BLK];
    int t = threadIdx.x;
    int i = blockIdx.x * SCAN_BLK + t;
    int v = (i < N_NODES) ? g_deg[i] : 0;
    s[t] = v;
    __syncthreads();
    #pragma unroll
    for (int off = 1; off < SCAN_BLK; off <<= 1) {
        int tmp = (t >= off) ? s[t - off] : 0;
        __syncthreads();
        if (t >= off) s[t] += tmp;
        __syncthreads();
    }
    if (i < N_NODES) g_scan[i] = s[t];
    if (t == SCAN_BLK - 1) g_bsum[blockIdx.x] = s[t];
}
__global__ void scan2_kernel() {
    __shared__ int s[SCAN_BLK];
    int t = threadIdx.x;
    int v = (t < NSCAN) ? g_bsum[t] : 0;
    s[t] = v;
    __syncthreads();
    #pragma unroll
    for (int off = 1; off < SCAN_BLK; off <<= 1) {
        int tmp = (t >= off) ? s[t - off] : 0;
        __syncthreads();
        if (t >= off) s[t] += tmp;
        __syncthreads();
    }
    if (t < NSCAN) g_bsum[t] = s[t] - v;
}
__global__ void scan3_kernel() {
    int i = blockIdx.x * SCAN_BLK + threadIdx.x;
    if (i < N_NODES) {
        int rs = g_scan[i] - g_deg[i] + g_bsum[blockIdx.x];
        g_rowstart[i] = rs;
        g_ptr[i] = rs;
    }
}

// ---------------- kernel: bucket edges by dst (proven R2) --------------------
__global__ void sort_kernel(const int* __restrict__ edge_index) {
    int e = blockIdx.x * blockDim.x + threadIdx.x;
    if (e >= N_EDGES) return;
    int src = edge_index[e];
    int dst = edge_index[N_EDGES + e];
    int pos = atomicAdd(&g_ptr[dst], 1);
    g_sorted_src[pos] = src;
    g_sorted_eid[pos] = e;
}

// ---------------- kernel: gather-aggregate (proven R2) -----------------------
__global__ void __launch_bounds__(256) aggregate_kernel(float* __restrict__ out) {
    int n    = (blockIdx.x * blockDim.x + threadIdx.x) >> 5;
    int lane = threadIdx.x & 31;
    if (n >= N_NODES) return;

    const int start = g_rowstart[n];
    const int deg   = g_deg[n];
    const float m   = __int_as_float(g_max_bits);

    float4 acc0 = make_float4(0.f, 0.f, 0.f, 0.f);
    float4 acc1 = make_float4(0.f, 0.f, 0.f, 0.f);
    float4 ds   = make_float4(0.f, 0.f, 0.f, 0.f);

    for (int i = 0; i < deg; i++) {
        int idx = start + i;
        int src = __ldg(&g_sorted_src[idx]);
        int eid = __ldg(&g_sorted_eid[idx]);
        float4 sc = *(const float4*)(g_e + (size_t)eid * 4);
        float4 ee;
        ee.x = __expf(sc.x - m);
        ee.y = __expf(sc.y - m);
        ee.z = __expf(sc.z - m);
        ee.w = __expf(sc.w - m);
        ds.x += ee.x; ds.y += ee.y; ds.z += ee.z; ds.w += ee.w;

        float alo = (lane < 16) ? ee.x : ee.y;   // heads 0/1
        float ahi = (lane < 16) ? ee.z : ee.w;   // heads 2/3
        const float4* hs = (const float4*)(g_h + (size_t)src * HO);
        float4 v0 = hs[lane];
        float4 v1 = hs[lane + 32];
        acc0.x = fmaf(v0.x, alo, acc0.x);
        acc0.y = fmaf(v0.y, alo, acc0.y);
        acc0.z = fmaf(v0.z, alo, acc0.z);
        acc0.w = fmaf(v0.w, alo, acc0.w);
        acc1.x = fmaf(v1.x, ahi, acc1.x);
        acc1.y = fmaf(v1.y, ahi, acc1.y);
        acc1.z = fmaf(v1.z, ahi, acc1.z);
        acc1.w = fmaf(v1.w, ahi, acc1.w);
    }

    float dlo = 1.0f / (((lane < 16) ? ds.x : ds.y) + 1e-10f);
    float dhi = 1.0f / (((lane < 16) ? ds.z : ds.w) + 1e-10f);
    float4* od = (float4*)(out + (size_t)n * HO);
    od[lane]      = make_float4(acc0.x * dlo, acc0.y * dlo, acc0.z * dlo, acc0.w * dlo);
    od[lane + 32] = make_float4(acc1.x * dhi, acc1.y * dhi, acc1.z * dhi, acc1.w * dhi);
}

// ---------------- launch ------------------------------------------------------
extern "C" void kernel_launch(void* const* d_in, const int* in_sizes, int n_in,
                              void* d_out, int out_size) {
    const float* x     = (const float*)d_in[0];
    const int*   eidx  = (const int*)  d_in[1];
    const float* ew    = (const float*)d_in[2];
    const float* W     = (const float*)d_in[3];
    const float* a_src = (const float*)d_in[4];
    const float* a_dst = (const float*)d_in[5];
    float* out = (float*)d_out;

    init_kernel<<<NSCAN, SCAN_BLK>>>();
    prep_b_kernel<<<128, 256>>>(W);

    dim3 ggrid((N_NODES + 127) / 128, 2);
    gemm_mma_kernel<<<ggrid, 256>>>(x);

    attn_kernel<<<(N_NODES * HEADS * 32 + 255) / 256, 256>>>(a_src, a_dst);

    edge_score_kernel<<<(N_EDGES + 255) / 256, 256>>>(eidx, ew);

    scan1_kernel<<<NSCAN, SCAN_BLK>>>();
    scan2_kernel<<<1, SCAN_BLK>>>();
    scan3_kernel<<<NSCAN, SCAN_BLK>>>();

    sort_kernel<<<(N_EDGES + 255) / 256, 256>>>(eidx);

    aggregate_kernel<<<(N_NODES * 32 + 255) / 256, 256>>>(out);
}